// round 10
// baseline (speedup 1.0000x reference)
#include <cuda_runtime.h>
#include <cuda_bf16.h>
#include <cstdint>

// ---------------------------------------------------------------------------
// SparseGATv2Layer: HMMA split-bf16 GEMM (in-kernel fp32->bf16 hi/lo split)
// + edge-sorted online-softmax GAT. Fork-join streams:
//   chain A (capture stream): initdetect -> hist -> scan(1 block) -> scatter
//   chain B (side stream)   : mma_gemm (self-contained, no prep)
//   join                    : gat_node (warp/dst, online softmax, unroll 4)
// ---------------------------------------------------------------------------

#define MAXN 50000
#define MAXE 800000
#define MAXET (MAXE + MAXN)

__device__ float    g_proj[MAXN * 128];
__device__ float2   g_edge_s[MAXET];
__device__ unsigned g_cnt[MAXN + 4];
__device__ unsigned g_off[MAXN + 1];
__device__ unsigned g_cur[MAXN];
__device__ int      g_idx64;

__device__ __forceinline__ uint32_t smem_to_u32(const void* p) {
    uint32_t a;
    asm("{ .reg .u64 t; cvta.to.shared.u64 t, %1; cvt.u32.u64 %0, t; }"
        : "=r"(a) : "l"(p));
    return a;
}

#define SWZ128(o) ((o) ^ (((o) >> 3) & 0x70))

#define LDSM_X4(r0, r1, r2, r3, addr) \
    asm volatile("ldmatrix.sync.aligned.m8n8.x4.shared.b16 {%0,%1,%2,%3}, [%4];" \
                 : "=r"(r0), "=r"(r1), "=r"(r2), "=r"(r3) : "r"(addr))

#define MMA16816(c, a, b) \
    asm volatile("mma.sync.aligned.m16n8k16.row.col.f32.bf16.bf16.f32 " \
                 "{%0,%1,%2,%3}, {%4,%5,%6,%7}, {%8,%9}, {%0,%1,%2,%3};" \
                 : "+f"((c)[0]), "+f"((c)[1]), "+f"((c)[2]), "+f"((c)[3]) \
                 : "r"((a)[0]), "r"((a)[1]), "r"((a)[2]), "r"((a)[3]), \
                   "r"((b)[0]), "r"((b)[1]))

// ---- edge-index accessor: int64 or int32, probed on device --------------------
__device__ __forceinline__ int load_idx(const void* ei, int i) {
    if (g_idx64)
        return (int)((const long long*)ei)[i];
    else
        return ((const int*)ei)[i];
}

// ================================================================================
// A1: zero histogram + dtype probe
// ================================================================================
__global__ void initdetect_kernel(const long long* ei, int probe, int N) {
    int i = blockIdx.x * blockDim.x + threadIdx.x;
    if (i == 0) { g_idx64 = 1; g_off[0] = 0; g_cur[0] = 0; }
    if (i < N + 4) g_cnt[i] = 0u;
    if (i < probe) {
        long long v = ei[i];
        if (v < 0 || v >= (long long)N) g_idx64 = 0;
    }
}

// ================================================================================
// A2: histogram of dst, 4 edges per thread
// ================================================================================
__global__ void hist_kernel(const void* __restrict__ ei, int E, int N) {
    int base = (blockIdx.x * blockDim.x + threadIdx.x) * 4;
    int Et = E + N;
    if (base >= Et) return;
    int d0 = -1, d1 = -1, d2 = -1, d3 = -1;
    d0 = (base < E) ? load_idx(ei, E + base) : (base - E);
    if (base + 1 < Et) d1 = (base + 1 < E) ? load_idx(ei, E + base + 1) : (base + 1 - E);
    if (base + 2 < Et) d2 = (base + 2 < E) ? load_idx(ei, E + base + 2) : (base + 2 - E);
    if (base + 3 < Et) d3 = (base + 3 < E) ? load_idx(ei, E + base + 3) : (base + 3 - E);
    atomicAdd(&g_cnt[d0], 1u);
    if (d1 >= 0) atomicAdd(&g_cnt[d1], 1u);
    if (d2 >= 0) atomicAdd(&g_cnt[d2], 1u);
    if (d3 >= 0) atomicAdd(&g_cnt[d3], 1u);
}

// ================================================================================
// A3: single-block exclusive scan, 4 elements/thread, 1024 threads.
// ================================================================================
__device__ __forceinline__ unsigned warp_incl_scan(unsigned v, int lane) {
#pragma unroll
    for (int d = 1; d < 32; d <<= 1) {
        unsigned t = __shfl_up_sync(0xffffffffu, v, d);
        if (lane >= d) v += t;
    }
    return v;
}

__global__ __launch_bounds__(1024) void scan_kernel(int N) {
    __shared__ unsigned wsum[32];
    __shared__ unsigned s_carry;
    const int tid = threadIdx.x;
    const int lane = tid & 31;
    const int wid = tid >> 5;
    if (tid == 0) s_carry = 0u;
    __syncthreads();

    for (int base = 0; base < N; base += 4096) {
        int i0 = base + tid * 4;
        uint4 v = (i0 < N) ? *(const uint4*)&g_cnt[i0] : make_uint4(0u, 0u, 0u, 0u);
        unsigned t = v.x + v.y + v.z + v.w;

        unsigned incl = warp_incl_scan(t, lane);
        if (lane == 31) wsum[wid] = incl;
        __syncthreads();
        if (wid == 0) wsum[lane] = warp_incl_scan(wsum[lane], lane);  // inclusive
        __syncthreads();

        unsigned carry = s_carry;
        unsigned excl = incl - t + ((wid > 0) ? wsum[wid - 1] : 0u) + carry;

        unsigned p1 = excl + v.x;
        unsigned p2 = p1 + v.y;
        unsigned p3 = p2 + v.z;
        unsigned p4 = p3 + v.w;
        if (i0     < N) { g_off[i0 + 1] = p1; if (i0 + 1 < N) g_cur[i0 + 1] = p1; }
        if (i0 + 1 < N) { g_off[i0 + 2] = p2; if (i0 + 2 < N) g_cur[i0 + 2] = p2; }
        if (i0 + 2 < N) { g_off[i0 + 3] = p3; if (i0 + 3 < N) g_cur[i0 + 3] = p3; }
        if (i0 + 3 < N) { g_off[i0 + 4] = p4; if (i0 + 4 < N) g_cur[i0 + 4] = p4; }

        __syncthreads();
        if (tid == 0) s_carry = carry + wsum[31];
        __syncthreads();
    }
}

// ================================================================================
// A4: counting-sort scatter, 2 edges per thread
// ================================================================================
__global__ void scatter_kernel(const void* __restrict__ ei,
                               const float* __restrict__ ea, int E, int N) {
    int base = (blockIdx.x * blockDim.x + threadIdx.x) * 2;
    int Et = E + N;
    if (base >= Et) return;
#pragma unroll
    for (int q = 0; q < 2; q++) {
        int i = base + q;
        if (i >= Et) break;
        int src, dst; float red;
        if (i < E) {
            src = load_idx(ei, i);
            dst = load_idx(ei, E + i);
            float2 e2 = ((const float2*)ea)[i];
            red = e2.x + 0.35f * e2.y;
        } else {
            src = dst = i - E;
            red = 1.0f;
        }
        unsigned pos = atomicAdd(&g_cur[dst], 1u);
        g_edge_s[pos] = make_float2(__int_as_float(src), red);
    }
}

// ================================================================================
// B1: HMMA split-bf16 GEMM with IN-KERNEL fp32 -> bf16 (hi, lo) split.
// CTA = 128 rows x 128 cols; grid.y==0 -> W_lin -> g_proj, ==1 -> W_res+bias -> out.
// D = Ah*Bh + Al*Bh + Ah*Bl, fp32 accumulate, K=128 (2 SMEM k-blocks of 64).
// ================================================================================
#define SA_HI 0
#define SA_LO 32768
#define SB_HI 65536
#define SB_LO 98304
#define GSM_TOTAL 131072

__device__ __forceinline__ void bf16_split_store8(char* hi_ptr, char* lo_ptr, float4 v) {
    __nv_bfloat16 hx = __float2bfloat16(v.x), hy = __float2bfloat16(v.y);
    __nv_bfloat16 hz = __float2bfloat16(v.z), hw = __float2bfloat16(v.w);
    __nv_bfloat162 h01; h01.x = hx; h01.y = hy;
    __nv_bfloat162 h23; h23.x = hz; h23.y = hw;
    __nv_bfloat162 l01, l23;
    l01.x = __float2bfloat16(v.x - __bfloat162float(hx));
    l01.y = __float2bfloat16(v.y - __bfloat162float(hy));
    l23.x = __float2bfloat16(v.z - __bfloat162float(hz));
    l23.y = __float2bfloat16(v.w - __bfloat162float(hw));
    uint2 hv; hv.x = *(uint32_t*)&h01; hv.y = *(uint32_t*)&h23;
    uint2 lv; lv.x = *(uint32_t*)&l01; lv.y = *(uint32_t*)&l23;
    *(uint2*)hi_ptr = hv;
    *(uint2*)lo_ptr = lv;
}

__global__ __launch_bounds__(256, 1) void mma_gemm_kernel(
    const float* __restrict__ x, const float* __restrict__ W_lin,
    const float* __restrict__ W_res, const float* __restrict__ bias,
    float* __restrict__ out, int N)
{
    extern __shared__ char smem[];
    const uint32_t sbase = smem_to_u32(smem);
    const int tid = threadIdx.x;
    const int lane = tid & 31;
    const int wid = tid >> 5;
    const int warpm = wid & 3;
    const int warpn = wid >> 2;
    const int rbase = blockIdx.x * 128;

    const float4* xf4 = (const float4*)x;
    const float4* wf4 = (const float4*)((blockIdx.y == 0) ? W_lin : W_res);
    const float4 zero4 = make_float4(0.f, 0.f, 0.f, 0.f);

    // stage + split: 4096 float4 for A, 4096 for B (16 each per thread)
#pragma unroll
    for (int idx = tid; idx < 4096; idx += 256) {
        int r = idx >> 5;            // row 0..127
        int c4 = idx & 31;           // float4 index within 128-col row
        int b = c4 >> 4;             // k-block (cols 0-63 / 64-127)
        uint32_t off = (uint32_t)(b * 16384) +
                       SWZ128((uint32_t)(r * 128 + (c4 & 15) * 8));
        int arow = rbase + r;
        float4 va = (arow < N) ? xf4[arow * 32 + c4] : zero4;
        bf16_split_store8(smem + SA_HI + off, smem + SA_LO + off, va);
        float4 vb = wf4[r * 32 + c4];
        bf16_split_store8(smem + SB_HI + off, smem + SB_LO + off, vb);
    }
    __syncthreads();

    float acc[2][8][4];
#pragma unroll
    for (int mt = 0; mt < 2; mt++)
#pragma unroll
        for (int nt = 0; nt < 8; nt++)
#pragma unroll
            for (int q = 0; q < 4; q++) acc[mt][nt][q] = 0.0f;

    const int a_row_off = lane & 15;
    const int a_seg = (lane >> 4) & 1;
    const int b_row_off = (lane & 7) + ((lane >> 4) & 1) * 8;
    const int b_seg = (lane >> 3) & 1;

#pragma unroll
    for (int b = 0; b < 2; b++) {
        const uint32_t ahb = sbase + SA_HI + b * 16384;
        const uint32_t alb = sbase + SA_LO + b * 16384;
        const uint32_t bhb = sbase + SB_HI + b * 16384;
        const uint32_t blb = sbase + SB_LO + b * 16384;
#pragma unroll
        for (int s = 0; s < 4; s++) {
            const int c0 = s * 16;
            uint32_t ah[8], al[8];
#pragma unroll
            for (int mt = 0; mt < 2; mt++) {
                int row = warpm * 32 + mt * 16 + a_row_off;
                uint32_t off = SWZ128((uint32_t)(row * 128 + (c0 + a_seg * 8) * 2));
                LDSM_X4(ah[mt*4], ah[mt*4+1], ah[mt*4+2], ah[mt*4+3], ahb + off);
                LDSM_X4(al[mt*4], al[mt*4+1], al[mt*4+2], al[mt*4+3], alb + off);
            }
            uint32_t bf[16];
#pragma unroll
            for (int p = 0; p < 4; p++) {
                int row = warpn * 64 + p * 16 + b_row_off;
                uint32_t off = SWZ128((uint32_t)(row * 128 + (c0 + b_seg * 8) * 2));
                LDSM_X4(bf[p*4], bf[p*4+1], bf[p*4+2], bf[p*4+3], bhb + off);
            }
#pragma unroll
            for (int mt = 0; mt < 2; mt++)
#pragma unroll
                for (int nt = 0; nt < 8; nt++) {
                    uint32_t* bb = &bf[(nt >> 1) * 4 + (nt & 1) * 2];
                    MMA16816(acc[mt][nt], &ah[mt*4], bb);   // hh
                    MMA16816(acc[mt][nt], &al[mt*4], bb);   // lh
                }
#pragma unroll
            for (int p = 0; p < 4; p++) {
                int row = warpn * 64 + p * 16 + b_row_off;
                uint32_t off = SWZ128((uint32_t)(row * 128 + (c0 + b_seg * 8) * 2));
                LDSM_X4(bf[p*4], bf[p*4+1], bf[p*4+2], bf[p*4+3], blb + off);
            }
#pragma unroll
            for (int mt = 0; mt < 2; mt++)
#pragma unroll
                for (int nt = 0; nt < 8; nt++) {
                    uint32_t* bb = &bf[(nt >> 1) * 4 + (nt & 1) * 2];
                    MMA16816(acc[mt][nt], &ah[mt*4], bb);   // hl
                }
        }
    }

    const int rr = lane >> 2;
    const int cc = (lane & 3) * 2;
#pragma unroll
    for (int mt = 0; mt < 2; mt++) {
        int row0 = rbase + warpm * 32 + mt * 16 + rr;
#pragma unroll
        for (int nt = 0; nt < 8; nt++) {
            int col = warpn * 64 + nt * 8 + cc;
            if (blockIdx.y == 0) {
                if (row0 < N)
                    *(float2*)&g_proj[row0 * 128 + col] =
                        make_float2(acc[mt][nt][0], acc[mt][nt][1]);
                if (row0 + 8 < N)
                    *(float2*)&g_proj[(row0 + 8) * 128 + col] =
                        make_float2(acc[mt][nt][2], acc[mt][nt][3]);
            } else {
                float2 bb = *(const float2*)&bias[col];
                if (row0 < N)
                    *(float2*)&out[row0 * 128 + col] =
                        make_float2(acc[mt][nt][0] + bb.x, acc[mt][nt][1] + bb.y);
                if (row0 + 8 < N)
                    *(float2*)&out[(row0 + 8) * 128 + col] =
                        make_float2(acc[mt][nt][2] + bb.x, acc[mt][nt][3] + bb.y);
            }
        }
    }
}

// ================================================================================
// J1: GAT node kernel, single pass online softmax, unroll 4 (R8 version)
// ================================================================================
struct EdgeCalc { float4 ps; float logit; };

__device__ __forceinline__ EdgeCalc edge_calc(float2 er, const float4* p4,
                                              float4 pd, float4 a4, float web,
                                              int lane)
{
    EdgeCalc r;
    int src = __float_as_int(er.x);
    r.ps = p4[src * 32 + lane];
    float zx = r.ps.x + pd.x; zx = fmaxf(zx, 0.2f * zx);
    float zy = r.ps.y + pd.y; zy = fmaxf(zy, 0.2f * zy);
    float zz = r.ps.z + pd.z; zz = fmaxf(zz, 0.2f * zz);
    float zw = r.ps.w + pd.w; zw = fmaxf(zw, 0.2f * zw);
    float part = zx * a4.x + zy * a4.y + zz * a4.z + zw * a4.w;
    part += __shfl_xor_sync(0xffffffffu, part, 4);
    part += __shfl_xor_sync(0xffffffffu, part, 2);
    part += __shfl_xor_sync(0xffffffffu, part, 1);
    r.logit = fmaf(er.y, web, part);
    return r;
}

__global__ __launch_bounds__(256) void gat_node_kernel(
    const float* __restrict__ att, const float* __restrict__ W_eb,
    float* __restrict__ out, int N)
{
    int warp = (blockIdx.x * blockDim.x + threadIdx.x) >> 5;
    int lane = threadIdx.x & 31;
    if (warp >= N) return;
    const int d = warp;
    const int h = lane >> 3;

    const int beg = (int)g_off[d];
    const int end = (int)g_off[d + 1];

    const float4* p4 = (const float4*)g_proj;
    float4 pd = p4[d * 32 + lane];
    float4 a4 = ((const float4*)att)[lane];
    float web = __ldg(&W_eb[h]);

    float m = -3.4e38f, den = 0.0f;
    float ax = 0.0f, ay = 0.0f, az = 0.0f, aw = 0.0f;

    int j = beg;
    for (; j + 3 < end; j += 4) {
        float2 er0 = g_edge_s[j];
        float2 er1 = g_edge_s[j + 1];
        float2 er2 = g_edge_s[j + 2];
        float2 er3 = g_edge_s[j + 3];
        EdgeCalc c0 = edge_calc(er0, p4, pd, a4, web, lane);
        EdgeCalc c1 = edge_calc(er1, p4, pd, a4, web, lane);
        EdgeCalc c2 = edge_calc(er2, p4, pd, a4, web, lane);
        EdgeCalc c3 = edge_calc(er3, p4, pd, a4, web, lane);

        float mnew = fmaxf(fmaxf(m, fmaxf(c0.logit, c1.logit)),
                           fmaxf(c2.logit, c3.logit));
        float s  = __expf(m - mnew);
        float p0 = __expf(c0.logit - mnew);
        float p1 = __expf(c1.logit - mnew);
        float p2 = __expf(c2.logit - mnew);
        float p3 = __expf(c3.logit - mnew);
        den = fmaf(den, s, (p0 + p1) + (p2 + p3));
        ax = fmaf(ax, s, fmaf(p0, c0.ps.x, p1 * c1.ps.x) + fmaf(p2, c2.ps.x, p3 * c3.ps.x));
        ay = fmaf(ay, s, fmaf(p0, c0.ps.y, p1 * c1.ps.y) + fmaf(p2, c2.ps.y, p3 * c3.ps.y));
        az = fmaf(az, s, fmaf(p0, c0.ps.z, p1 * c1.ps.z) + fmaf(p2, c2.ps.z, p3 * c3.ps.z));
        aw = fmaf(aw, s, fmaf(p0, c0.ps.w, p1 * c1.ps.w) + fmaf(p2, c2.ps.w, p3 * c3.ps.w));
        m = mnew;
    }
    for (; j < end; ++j) {
        float2 er0 = g_edge_s[j];
        EdgeCalc c0 = edge_calc(er0, p4, pd, a4, web, lane);
        float mnew = fmaxf(m, c0.logit);
        float s = __expf(m - mnew);
        float p0 = __expf(c0.logit - mnew);
        den = fmaf(den, s, p0);
        ax = fmaf(ax, s, p0 * c0.ps.x);
        ay = fmaf(ay, s, p0 * c0.ps.y);
        az = fmaf(az, s, p0 * c0.ps.z);
        aw = fmaf(aw, s, p0 * c0.ps.w);
        m = mnew;
    }

    float inv = 1.0f / fmaxf(den, 1e-12f);
    float4* o4 = (float4*)out;
    float4 r = o4[d * 32 + lane];
    r.x = fmaf(ax, inv, r.x);
    r.y = fmaf(ay, inv, r.y);
    r.z = fmaf(az, inv, r.z);
    r.w = fmaf(aw, inv, r.w);
    o4[d * 32 + lane] = r;
}

// ================================================================================
extern "C" void kernel_launch(void* const* d_in, const int* in_sizes, int n_in,
                              void* d_out, int out_size)
{
    const float* x     = (const float*)d_in[0];
    const void*  ei    = (const void*)d_in[1];
    const float* ea    = (const float*)d_in[2];
    const float* W_lin = (const float*)d_in[3];
    const float* att   = (const float*)d_in[4];
    const float* W_eb  = (const float*)d_in[5];
    const float* bias  = (const float*)d_in[6];
    const float* W_res = (const float*)d_in[7];
    float* out = (float*)d_out;

    int N  = in_sizes[0] / 128;
    int E  = in_sizes[1] / 2;
    int Et = E + N;

    static cudaStream_t s_gemm = nullptr;
    static cudaEvent_t ev_fork = nullptr, ev_join = nullptr;
    if (s_gemm == nullptr) {
        cudaStreamCreateWithFlags(&s_gemm, cudaStreamNonBlocking);
        cudaEventCreateWithFlags(&ev_fork, cudaEventDisableTiming);
        cudaEventCreateWithFlags(&ev_join, cudaEventDisableTiming);
        cudaFuncSetAttribute(mma_gemm_kernel,
                             cudaFuncAttributeMaxDynamicSharedMemorySize, GSM_TOTAL);
    }

    // ---- fork: GEMM on side stream (self-contained, no prep) ----
    cudaEventRecord(ev_fork, 0);
    cudaStreamWaitEvent(s_gemm, ev_fork, 0);
    mma_gemm_kernel<<<dim3((N + 127) / 128, 2), 256, GSM_TOTAL, s_gemm>>>(
        x, W_lin, W_res, bias, out, N);
    cudaEventRecord(ev_join, s_gemm);

    // ---- edge chain on capture stream ----
    int probe = (E < 65536) ? E : 65536;
    int initThreads = (N + 4 > probe) ? (N + 4) : probe;
    initdetect_kernel<<<(initThreads + 255) / 256, 256>>>((const long long*)ei, probe, N);
    hist_kernel<<<(Et / 4 + 256) / 256, 256>>>(ei, E, N);
    scan_kernel<<<1, 1024>>>(N);
    scatter_kernel<<<(Et / 2 + 256) / 256, 256>>>(ei, ea, E, N);

    // ---- join, then node kernel ----
    cudaStreamWaitEvent(0, ev_join, 0);
    gat_node_kernel<<<(N * 32 + 255) / 256, 256>>>(att, W_eb, out, N);
}

// round 11
// speedup vs baseline: 1.2237x; 1.2237x over previous
#include <cuda_runtime.h>
#include <cuda_bf16.h>
#include <cstdint>

// ---------------------------------------------------------------------------
// SparseGATv2Layer: HMMA split-bf16 GEMM (in-kernel fp32->bf16 hi/lo split)
// + edge-sorted online-softmax GAT. Fork-join streams:
//   chain A (capture stream): initdetect -> hist -> scan x3 -> scatter
//   chain B (side stream)   : mma_gemm (self-contained, no prep)
//   join                    : gat_node (warp/dst, online softmax, unroll 4)
// ---------------------------------------------------------------------------

#define MAXN 50000
#define MAXE 800000
#define MAXET (MAXE + MAXN)

__device__ float    g_proj[MAXN * 128];
__device__ float2   g_edge_s[MAXET];
__device__ unsigned g_cnt[MAXN + 4];
__device__ unsigned g_tmp[MAXN];
__device__ unsigned g_bsum[1024];
__device__ unsigned g_off[MAXN + 1];
__device__ unsigned g_cur[MAXN];
__device__ int      g_idx64;

__device__ __forceinline__ uint32_t smem_to_u32(const void* p) {
    uint32_t a;
    asm("{ .reg .u64 t; cvta.to.shared.u64 t, %1; cvt.u32.u64 %0, t; }"
        : "=r"(a) : "l"(p));
    return a;
}

#define SWZ128(o) ((o) ^ (((o) >> 3) & 0x70))

#define LDSM_X4(r0, r1, r2, r3, addr) \
    asm volatile("ldmatrix.sync.aligned.m8n8.x4.shared.b16 {%0,%1,%2,%3}, [%4];" \
                 : "=r"(r0), "=r"(r1), "=r"(r2), "=r"(r3) : "r"(addr))

#define MMA16816(c, a, b) \
    asm volatile("mma.sync.aligned.m16n8k16.row.col.f32.bf16.bf16.f32 " \
                 "{%0,%1,%2,%3}, {%4,%5,%6,%7}, {%8,%9}, {%0,%1,%2,%3};" \
                 : "+f"((c)[0]), "+f"((c)[1]), "+f"((c)[2]), "+f"((c)[3]) \
                 : "r"((a)[0]), "r"((a)[1]), "r"((a)[2]), "r"((a)[3]), \
                   "r"((b)[0]), "r"((b)[1]))

// ---- edge-index accessor: int64 or int32, probed on device --------------------
__device__ __forceinline__ int load_idx(const void* ei, int i) {
    if (g_idx64)
        return (int)((const long long*)ei)[i];
    else
        return ((const int*)ei)[i];
}

// ================================================================================
// A1: zero histogram + dtype probe
// ================================================================================
__global__ void initdetect_kernel(const long long* ei, int probe, int N) {
    int i = blockIdx.x * blockDim.x + threadIdx.x;
    if (i == 0) { g_idx64 = 1; g_off[0] = 0; g_cur[0] = 0; }
    if (i < N + 4) g_cnt[i] = 0u;
    if (i < probe) {
        long long v = ei[i];
        if (v < 0 || v >= (long long)N) g_idx64 = 0;
    }
}

// ================================================================================
// A2: histogram of dst, 4 edges per thread
// ================================================================================
__global__ void hist_kernel(const void* __restrict__ ei, int E, int N) {
    int base = (blockIdx.x * blockDim.x + threadIdx.x) * 4;
    int Et = E + N;
    if (base >= Et) return;
    int d0 = -1, d1 = -1, d2 = -1, d3 = -1;
    d0 = (base < E) ? load_idx(ei, E + base) : (base - E);
    if (base + 1 < Et) d1 = (base + 1 < E) ? load_idx(ei, E + base + 1) : (base + 1 - E);
    if (base + 2 < Et) d2 = (base + 2 < E) ? load_idx(ei, E + base + 2) : (base + 2 - E);
    if (base + 3 < Et) d3 = (base + 3 < E) ? load_idx(ei, E + base + 3) : (base + 3 - E);
    atomicAdd(&g_cnt[d0], 1u);
    if (d1 >= 0) atomicAdd(&g_cnt[d1], 1u);
    if (d2 >= 0) atomicAdd(&g_cnt[d2], 1u);
    if (d3 >= 0) atomicAdd(&g_cnt[d3], 1u);
}

// ---- A3-A5: 3-kernel warp-shuffle scan (R8 version: 4.5+1+1 us) -----------------
__device__ __forceinline__ unsigned warp_incl_scan(unsigned v, int lane) {
#pragma unroll
    for (int d = 1; d < 32; d <<= 1) {
        unsigned t = __shfl_up_sync(0xffffffffu, v, d);
        if (lane >= d) v += t;
    }
    return v;
}

__global__ void scan1_kernel(int N) {
    __shared__ unsigned wsum[32];
    int i = blockIdx.x * 1024 + threadIdx.x;
    int lane = threadIdx.x & 31;
    int wid = threadIdx.x >> 5;
    unsigned v = (i < N) ? g_cnt[i] : 0u;
    unsigned incl = warp_incl_scan(v, lane);
    if (lane == 31) wsum[wid] = incl;
    __syncthreads();
    if (wid == 0) {
        unsigned w = wsum[lane];
        wsum[lane] = warp_incl_scan(w, lane) - w;
    }
    __syncthreads();
    incl += wsum[wid];
    if (i < N) g_tmp[i] = incl;
    if (threadIdx.x == 1023) g_bsum[blockIdx.x] = incl;
}

__global__ void scan2_kernel(int nb) {
    __shared__ unsigned wsum[32];
    int lane = threadIdx.x & 31;
    int wid = threadIdx.x >> 5;
    unsigned v = (threadIdx.x < nb) ? g_bsum[threadIdx.x] : 0u;
    unsigned incl = warp_incl_scan(v, lane);
    if (lane == 31) wsum[wid] = incl;
    __syncthreads();
    if (wid == 0) {
        unsigned w = wsum[lane];
        wsum[lane] = warp_incl_scan(w, lane) - w;
    }
    __syncthreads();
    incl += wsum[wid];
    if (threadIdx.x < nb) g_bsum[threadIdx.x] = incl - v;
}

__global__ void scan3_kernel(int N) {
    int i = blockIdx.x * 1024 + threadIdx.x;
    if (i >= N) return;
    unsigned incl = g_tmp[i] + g_bsum[blockIdx.x];
    g_off[i + 1] = incl;
    if (i + 1 < N) g_cur[i + 1] = incl;
}

// ================================================================================
// A6: counting-sort scatter, 2 edges per thread
// ================================================================================
__global__ void scatter_kernel(const void* __restrict__ ei,
                               const float* __restrict__ ea, int E, int N) {
    int base = (blockIdx.x * blockDim.x + threadIdx.x) * 2;
    int Et = E + N;
    if (base >= Et) return;
#pragma unroll
    for (int q = 0; q < 2; q++) {
        int i = base + q;
        if (i >= Et) break;
        int src, dst; float red;
        if (i < E) {
            src = load_idx(ei, i);
            dst = load_idx(ei, E + i);
            float2 e2 = ((const float2*)ea)[i];
            red = e2.x + 0.35f * e2.y;
        } else {
            src = dst = i - E;
            red = 1.0f;
        }
        unsigned pos = atomicAdd(&g_cur[dst], 1u);
        g_edge_s[pos] = make_float2(__int_as_float(src), red);
    }
}

// ================================================================================
// B1: HMMA split-bf16 GEMM with IN-KERNEL fp32 -> bf16 (hi, lo) split.
// CTA = 128 rows x 128 cols; grid.y==0 -> W_lin -> g_proj, ==1 -> W_res+bias -> out.
// ================================================================================
#define SA_HI 0
#define SA_LO 32768
#define SB_HI 65536
#define SB_LO 98304
#define GSM_TOTAL 131072

__device__ __forceinline__ void bf16_split_store8(char* hi_ptr, char* lo_ptr, float4 v) {
    __nv_bfloat16 hx = __float2bfloat16(v.x), hy = __float2bfloat16(v.y);
    __nv_bfloat16 hz = __float2bfloat16(v.z), hw = __float2bfloat16(v.w);
    __nv_bfloat162 h01; h01.x = hx; h01.y = hy;
    __nv_bfloat162 h23; h23.x = hz; h23.y = hw;
    __nv_bfloat162 l01, l23;
    l01.x = __float2bfloat16(v.x - __bfloat162float(hx));
    l01.y = __float2bfloat16(v.y - __bfloat162float(hy));
    l23.x = __float2bfloat16(v.z - __bfloat162float(hz));
    l23.y = __float2bfloat16(v.w - __bfloat162float(hw));
    uint2 hv; hv.x = *(uint32_t*)&h01; hv.y = *(uint32_t*)&h23;
    uint2 lv; lv.x = *(uint32_t*)&l01; lv.y = *(uint32_t*)&l23;
    *(uint2*)hi_ptr = hv;
    *(uint2*)lo_ptr = lv;
}

__global__ __launch_bounds__(256, 1) void mma_gemm_kernel(
    const float* __restrict__ x, const float* __restrict__ W_lin,
    const float* __restrict__ W_res, const float* __restrict__ bias,
    float* __restrict__ out, int N)
{
    extern __shared__ char smem[];
    const uint32_t sbase = smem_to_u32(smem);
    const int tid = threadIdx.x;
    const int lane = tid & 31;
    const int wid = tid >> 5;
    const int warpm = wid & 3;
    const int warpn = wid >> 2;
    const int rbase = blockIdx.x * 128;

    const float4* xf4 = (const float4*)x;
    const float4* wf4 = (const float4*)((blockIdx.y == 0) ? W_lin : W_res);
    const float4 zero4 = make_float4(0.f, 0.f, 0.f, 0.f);

#pragma unroll
    for (int idx = tid; idx < 4096; idx += 256) {
        int r = idx >> 5;
        int c4 = idx & 31;
        int b = c4 >> 4;
        uint32_t off = (uint32_t)(b * 16384) +
                       SWZ128((uint32_t)(r * 128 + (c4 & 15) * 8));
        int arow = rbase + r;
        float4 va = (arow < N) ? xf4[arow * 32 + c4] : zero4;
        bf16_split_store8(smem + SA_HI + off, smem + SA_LO + off, va);
        float4 vb = wf4[r * 32 + c4];
        bf16_split_store8(smem + SB_HI + off, smem + SB_LO + off, vb);
    }
    __syncthreads();

    float acc[2][8][4];
#pragma unroll
    for (int mt = 0; mt < 2; mt++)
#pragma unroll
        for (int nt = 0; nt < 8; nt++)
#pragma unroll
            for (int q = 0; q < 4; q++) acc[mt][nt][q] = 0.0f;

    const int a_row_off = lane & 15;
    const int a_seg = (lane >> 4) & 1;
    const int b_row_off = (lane & 7) + ((lane >> 4) & 1) * 8;
    const int b_seg = (lane >> 3) & 1;

#pragma unroll
    for (int b = 0; b < 2; b++) {
        const uint32_t ahb = sbase + SA_HI + b * 16384;
        const uint32_t alb = sbase + SA_LO + b * 16384;
        const uint32_t bhb = sbase + SB_HI + b * 16384;
        const uint32_t blb = sbase + SB_LO + b * 16384;
#pragma unroll
        for (int s = 0; s < 4; s++) {
            const int c0 = s * 16;
            uint32_t ah[8], al[8];
#pragma unroll
            for (int mt = 0; mt < 2; mt++) {
                int row = warpm * 32 + mt * 16 + a_row_off;
                uint32_t off = SWZ128((uint32_t)(row * 128 + (c0 + a_seg * 8) * 2));
                LDSM_X4(ah[mt*4], ah[mt*4+1], ah[mt*4+2], ah[mt*4+3], ahb + off);
                LDSM_X4(al[mt*4], al[mt*4+1], al[mt*4+2], al[mt*4+3], alb + off);
            }
            uint32_t bf[16];
#pragma unroll
            for (int p = 0; p < 4; p++) {
                int row = warpn * 64 + p * 16 + b_row_off;
                uint32_t off = SWZ128((uint32_t)(row * 128 + (c0 + b_seg * 8) * 2));
                LDSM_X4(bf[p*4], bf[p*4+1], bf[p*4+2], bf[p*4+3], bhb + off);
            }
#pragma unroll
            for (int mt = 0; mt < 2; mt++)
#pragma unroll
                for (int nt = 0; nt < 8; nt++) {
                    uint32_t* bb = &bf[(nt >> 1) * 4 + (nt & 1) * 2];
                    MMA16816(acc[mt][nt], &ah[mt*4], bb);   // hh
                    MMA16816(acc[mt][nt], &al[mt*4], bb);   // lh
                }
#pragma unroll
            for (int p = 0; p < 4; p++) {
                int row = warpn * 64 + p * 16 + b_row_off;
                uint32_t off = SWZ128((uint32_t)(row * 128 + (c0 + b_seg * 8) * 2));
                LDSM_X4(bf[p*4], bf[p*4+1], bf[p*4+2], bf[p*4+3], blb + off);
            }
#pragma unroll
            for (int mt = 0; mt < 2; mt++)
#pragma unroll
                for (int nt = 0; nt < 8; nt++) {
                    uint32_t* bb = &bf[(nt >> 1) * 4 + (nt & 1) * 2];
                    MMA16816(acc[mt][nt], &ah[mt*4], bb);   // hl
                }
        }
    }

    const int rr = lane >> 2;
    const int cc = (lane & 3) * 2;
#pragma unroll
    for (int mt = 0; mt < 2; mt++) {
        int row0 = rbase + warpm * 32 + mt * 16 + rr;
#pragma unroll
        for (int nt = 0; nt < 8; nt++) {
            int col = warpn * 64 + nt * 8 + cc;
            if (blockIdx.y == 0) {
                if (row0 < N)
                    *(float2*)&g_proj[row0 * 128 + col] =
                        make_float2(acc[mt][nt][0], acc[mt][nt][1]);
                if (row0 + 8 < N)
                    *(float2*)&g_proj[(row0 + 8) * 128 + col] =
                        make_float2(acc[mt][nt][2], acc[mt][nt][3]);
            } else {
                float2 bb = *(const float2*)&bias[col];
                if (row0 < N)
                    *(float2*)&out[row0 * 128 + col] =
                        make_float2(acc[mt][nt][0] + bb.x, acc[mt][nt][1] + bb.y);
                if (row0 + 8 < N)
                    *(float2*)&out[(row0 + 8) * 128 + col] =
                        make_float2(acc[mt][nt][2] + bb.x, acc[mt][nt][3] + bb.y);
            }
        }
    }
}

// ================================================================================
// J1: GAT node kernel, single pass online softmax, unroll 4 (R8 version)
// ================================================================================
struct EdgeCalc { float4 ps; float logit; };

__device__ __forceinline__ EdgeCalc edge_calc(float2 er, const float4* p4,
                                              float4 pd, float4 a4, float web,
                                              int lane)
{
    EdgeCalc r;
    int src = __float_as_int(er.x);
    r.ps = p4[src * 32 + lane];
    float zx = r.ps.x + pd.x; zx = fmaxf(zx, 0.2f * zx);
    float zy = r.ps.y + pd.y; zy = fmaxf(zy, 0.2f * zy);
    float zz = r.ps.z + pd.z; zz = fmaxf(zz, 0.2f * zz);
    float zw = r.ps.w + pd.w; zw = fmaxf(zw, 0.2f * zw);
    float part = zx * a4.x + zy * a4.y + zz * a4.z + zw * a4.w;
    part += __shfl_xor_sync(0xffffffffu, part, 4);
    part += __shfl_xor_sync(0xffffffffu, part, 2);
    part += __shfl_xor_sync(0xffffffffu, part, 1);
    r.logit = fmaf(er.y, web, part);
    return r;
}

__global__ __launch_bounds__(256) void gat_node_kernel(
    const float* __restrict__ att, const float* __restrict__ W_eb,
    float* __restrict__ out, int N)
{
    int warp = (blockIdx.x * blockDim.x + threadIdx.x) >> 5;
    int lane = threadIdx.x & 31;
    if (warp >= N) return;
    const int d = warp;
    const int h = lane >> 3;

    const int beg = (int)g_off[d];
    const int end = (int)g_off[d + 1];

    const float4* p4 = (const float4*)g_proj;
    float4 pd = p4[d * 32 + lane];
    float4 a4 = ((const float4*)att)[lane];
    float web = __ldg(&W_eb[h]);

    float m = -3.4e38f, den = 0.0f;
    float ax = 0.0f, ay = 0.0f, az = 0.0f, aw = 0.0f;

    int j = beg;
    for (; j + 3 < end; j += 4) {
        float2 er0 = g_edge_s[j];
        float2 er1 = g_edge_s[j + 1];
        float2 er2 = g_edge_s[j + 2];
        float2 er3 = g_edge_s[j + 3];
        EdgeCalc c0 = edge_calc(er0, p4, pd, a4, web, lane);
        EdgeCalc c1 = edge_calc(er1, p4, pd, a4, web, lane);
        EdgeCalc c2 = edge_calc(er2, p4, pd, a4, web, lane);
        EdgeCalc c3 = edge_calc(er3, p4, pd, a4, web, lane);

        float mnew = fmaxf(fmaxf(m, fmaxf(c0.logit, c1.logit)),
                           fmaxf(c2.logit, c3.logit));
        float s  = __expf(m - mnew);
        float p0 = __expf(c0.logit - mnew);
        float p1 = __expf(c1.logit - mnew);
        float p2 = __expf(c2.logit - mnew);
        float p3 = __expf(c3.logit - mnew);
        den = fmaf(den, s, (p0 + p1) + (p2 + p3));
        ax = fmaf(ax, s, fmaf(p0, c0.ps.x, p1 * c1.ps.x) + fmaf(p2, c2.ps.x, p3 * c3.ps.x));
        ay = fmaf(ay, s, fmaf(p0, c0.ps.y, p1 * c1.ps.y) + fmaf(p2, c2.ps.y, p3 * c3.ps.y));
        az = fmaf(az, s, fmaf(p0, c0.ps.z, p1 * c1.ps.z) + fmaf(p2, c2.ps.z, p3 * c3.ps.z));
        aw = fmaf(aw, s, fmaf(p0, c0.ps.w, p1 * c1.ps.w) + fmaf(p2, c2.ps.w, p3 * c3.ps.w));
        m = mnew;
    }
    for (; j < end; ++j) {
        float2 er0 = g_edge_s[j];
        EdgeCalc c0 = edge_calc(er0, p4, pd, a4, web, lane);
        float mnew = fmaxf(m, c0.logit);
        float s = __expf(m - mnew);
        float p0 = __expf(c0.logit - mnew);
        den = fmaf(den, s, p0);
        ax = fmaf(ax, s, p0 * c0.ps.x);
        ay = fmaf(ay, s, p0 * c0.ps.y);
        az = fmaf(az, s, p0 * c0.ps.z);
        aw = fmaf(aw, s, p0 * c0.ps.w);
        m = mnew;
    }

    float inv = 1.0f / fmaxf(den, 1e-12f);
    float4* o4 = (float4*)out;
    float4 r = o4[d * 32 + lane];
    r.x = fmaf(ax, inv, r.x);
    r.y = fmaf(ay, inv, r.y);
    r.z = fmaf(az, inv, r.z);
    r.w = fmaf(aw, inv, r.w);
    o4[d * 32 + lane] = r;
}

// ================================================================================
extern "C" void kernel_launch(void* const* d_in, const int* in_sizes, int n_in,
                              void* d_out, int out_size)
{
    const float* x     = (const float*)d_in[0];
    const void*  ei    = (const void*)d_in[1];
    const float* ea    = (const float*)d_in[2];
    const float* W_lin = (const float*)d_in[3];
    const float* att   = (const float*)d_in[4];
    const float* W_eb  = (const float*)d_in[5];
    const float* bias  = (const float*)d_in[6];
    const float* W_res = (const float*)d_in[7];
    float* out = (float*)d_out;

    int N  = in_sizes[0] / 128;
    int E  = in_sizes[1] / 2;
    int Et = E + N;
    int nb = (N + 1023) / 1024;

    static cudaStream_t s_gemm = nullptr;
    static cudaEvent_t ev_fork = nullptr, ev_join = nullptr;
    if (s_gemm == nullptr) {
        cudaStreamCreateWithFlags(&s_gemm, cudaStreamNonBlocking);
        cudaEventCreateWithFlags(&ev_fork, cudaEventDisableTiming);
        cudaEventCreateWithFlags(&ev_join, cudaEventDisableTiming);
        cudaFuncSetAttribute(mma_gemm_kernel,
                             cudaFuncAttributeMaxDynamicSharedMemorySize, GSM_TOTAL);
    }

    // ---- fork: GEMM on side stream (self-contained, no prep) ----
    cudaEventRecord(ev_fork, 0);
    cudaStreamWaitEvent(s_gemm, ev_fork, 0);
    mma_gemm_kernel<<<dim3((N + 127) / 128, 2), 256, GSM_TOTAL, s_gemm>>>(
        x, W_lin, W_res, bias, out, N);
    cudaEventRecord(ev_join, s_gemm);

    // ---- edge chain on capture stream ----
    int probe = (E < 65536) ? E : 65536;
    int initThreads = (N + 4 > probe) ? (N + 4) : probe;
    initdetect_kernel<<<(initThreads + 255) / 256, 256>>>((const long long*)ei, probe, N);
    hist_kernel<<<(Et / 4 + 256) / 256, 256>>>(ei, E, N);
    scan1_kernel<<<nb, 1024>>>(N);
    scan2_kernel<<<1, 1024>>>(nb);
    scan3_kernel<<<nb, 1024>>>(N);
    scatter_kernel<<<(Et / 2 + 256) / 256, 256>>>(ei, ea, E, N);

    // ---- join, then node kernel ----
    cudaStreamWaitEvent(0, ev_join, 0);
    gat_node_kernel<<<(N * 32 + 255) / 256, 256>>>(att, W_eb, out, N);
}